// round 13
// baseline (speedup 1.0000x reference)
#include <cuda_runtime.h>
#include <cuda_fp16.h>
#include <cstdint>

// ---------------------------------------------------------------------------
// CompressedLinear: y = ((x @ Vh^T) * S) @ U^T + bias
// mma.sync fp16 path. R12 falsified 8-warp LDSM (L1 +50%, tensor down);
// R11 config (4 warps @ 64x64, all-LDSM, NSTG=3, 2 CTAs/SM) is the mainloop
// optimum. This round: fold the x fp32->fp16 pass into the fused kernel as
// 256 convert-CTAs gated by xflags, overlapping conversion with GEMM1.
// ---------------------------------------------------------------------------

#define M_TOK   8192
#define IN_F    4096
#define OUT_F   4096
#define RANK    1024

#define TM      128
#define TN      128
#define XC_PER_MB   4                              // 4 convert CTAs per m-block
#define XC_TILES    (MBLKS * XC_PER_MB)            // 256
#define G1_TN_TILES (RANK / TN)                    // 8
#define G1_TILES    ((M_TOK / TM) * G1_TN_TILES)   // 512
#define G2_TN_TILES (OUT_F / TN)                   // 32
#define G2_TILES    ((M_TOK / TM) * G2_TN_TILES)   // 2048
#define MBLKS       (M_TOK / TM)                   // 64

__device__ __half g_x16[(size_t)M_TOK * IN_F];   // 64 MB (fp16 x)
__device__ __half g_W1[(size_t)RANK * IN_F];     // 8 MB  (Vh - 128)
__device__ __half g_W2[(size_t)OUT_F * RANK];    // 8 MB  (U - 128)
__device__ __half g_H [(size_t)M_TOK * RANK];    // 16 MB (h * hscale)
__device__ float  g_hscale[RANK];
__device__ int    g_flags[MBLKS];
__device__ int    g_xflags[MBLKS];

// ------------------------- prep kernel (weights only) -----------------------
#define NW1_CH  ((size_t)RANK * IN_F / 4)        // 1,048,576
#define NW2_CH  ((size_t)OUT_F * RANK / 4)       // 1,048,576

__global__ void prep_all(const int* __restrict__ Vh_data, const float* __restrict__ Vh_zp,
                         const int* __restrict__ U_data,  const float* __restrict__ U_zp,
                         const int* __restrict__ S_data,  const float* __restrict__ S_scale,
                         const float* __restrict__ S_zp,  const float* __restrict__ Vh_scale) {
    size_t g = (size_t)blockIdx.x * blockDim.x + threadIdx.x;
    if (g < NW1_CH) {
        size_t i = g * 4;
        float z = *Vh_zp;
        int4 d = *(const int4*)(Vh_data + i);
        *(__half2*)(g_W1 + i)     = __floats2half2_rn((float)d.x - z, (float)d.y - z);
        *(__half2*)(g_W1 + i + 2) = __floats2half2_rn((float)d.z - z, (float)d.w - z);
    } else if (g < NW1_CH + NW2_CH) {
        size_t i = (g - NW1_CH) * 4;
        float z = *U_zp;
        int4 d = *(const int4*)(U_data + i);
        *(__half2*)(g_W2 + i)     = __floats2half2_rn((float)d.x - z, (float)d.y - z);
        *(__half2*)(g_W2 + i + 2) = __floats2half2_rn((float)d.z - z, (float)d.w - z);
    } else if (g < NW1_CH + NW2_CH + RANK) {
        int r = (int)(g - NW1_CH - NW2_CH);
        g_hscale[r] = Vh_scale[0] * S_scale[0] * ((float)S_data[r] - S_zp[0]);
    } else if (g < NW1_CH + NW2_CH + RANK + MBLKS) {
        g_flags[g - NW1_CH - NW2_CH - RANK] = 0;
    } else if (g < NW1_CH + NW2_CH + RANK + 2 * MBLKS) {
        g_xflags[g - NW1_CH - NW2_CH - RANK - MBLKS] = 0;
    }
}

// ---------------------------- PTX helpers ----------------------------------
__device__ __forceinline__ void cp_async16(uint32_t saddr, const void* gp) {
    asm volatile("cp.async.cg.shared.global [%0], [%1], 16;\n" :: "r"(saddr), "l"(gp));
}
__device__ __forceinline__ void cp_commit() { asm volatile("cp.async.commit_group;\n"); }
template<int N> __device__ __forceinline__ void cp_wait() {
    asm volatile("cp.async.wait_group %0;\n" :: "n"(N));
}
__device__ __forceinline__ void mma16816(float* d, const uint32_t* a, const uint32_t* b) {
    asm volatile(
        "mma.sync.aligned.m16n8k16.row.col.f32.f16.f16.f32 "
        "{%0,%1,%2,%3}, {%4,%5,%6,%7}, {%8,%9}, {%0,%1,%2,%3};\n"
        : "+f"(d[0]), "+f"(d[1]), "+f"(d[2]), "+f"(d[3])
        : "r"(a[0]), "r"(a[1]), "r"(a[2]), "r"(a[3]), "r"(b[0]), "r"(b[1]));
}
__device__ __forceinline__ int ld_acquire_gpu(const int* p) {
    int v;
    asm volatile("ld.acquire.gpu.s32 %0, [%1];" : "=r"(v) : "l"(p) : "memory");
    return v;
}
__device__ __forceinline__ void ldsm_x4(uint32_t& r0, uint32_t& r1,
                                        uint32_t& r2, uint32_t& r3, uint32_t saddr) {
    asm volatile("ldmatrix.sync.aligned.m8n8.x4.shared.b16 {%0,%1,%2,%3}, [%4];"
                 : "=r"(r0), "=r"(r1), "=r"(r2), "=r"(r3) : "r"(saddr));
}

// ----------------------------- GEMM body -----------------------------------
#define BKH     64
#define NSTG    3
#define SROW    72
#define A_BYTES (TM * SROW * 2)             // 18432
#define B_BYTES (TN * SROW * 2)             // 18432
#define STG_BYTES (A_BYTES + B_BYTES)       // 36864
#define SMEM_USE (NSTG * STG_BYTES)         // 110592

// MODE 0 (GEMM1): C half, *= vec[col].  MODE 1 (GEMM2): C float, *us + vec.
// 4 warps, warp grid 2x2: warp tile 64x64. All fp16, all LDSM. (R11 config.)
template<int MODE>
__device__ __forceinline__ void
gemm_body(const __half* __restrict__ A, const __half* __restrict__ B,
          void* __restrict__ Cv, int N, int K,
          const float* __restrict__ vec, float us,
          int m0, int n0, char* smc) {
    const uint32_t smem_base = (uint32_t)__cvta_generic_to_shared(smc);

    const int tid  = threadIdx.x;
    const int warp = tid >> 5;
    const int lane = tid & 31;
    const int wm = (warp >> 1) * 64;        // 0 / 64
    const int wn = (warp & 1) * 64;         // 0 / 64
    const int g  = lane >> 2;
    const int tg = lane & 3;
    const int KT = K / BKH;

    const int a_row = (lane & 15);
    const int a_col = (lane >> 4) << 3;
    const int b_row = ((lane >> 4) << 3) + (lane & 7);
    const int b_col = ((lane >> 3) & 1) << 3;

    auto load_stage = [&](int kt, int s) {
        const uint32_t tA = smem_base + (uint32_t)(s * STG_BYTES);
        const uint32_t tB = tA + A_BYTES;
        const __half* gA = A + (size_t)m0 * K + (size_t)kt * BKH;
        const __half* gB = B + (size_t)n0 * K + (size_t)kt * BKH;
#pragma unroll
        for (int r = 0; r < 8; r++) {               // 1024 chunks: 128 rows x 8
            int i = tid + r * 128;
            int row = i >> 3, c = i & 7;
            cp_async16(tA + (uint32_t)(row * SROW + c * 8) * 2,
                       gA + (size_t)row * K + c * 8);
        }
#pragma unroll
        for (int r = 0; r < 8; r++) {
            int i = tid + r * 128;
            int row = i >> 3, c = i & 7;
            cp_async16(tB + (uint32_t)(row * SROW + c * 8) * 2,
                       gB + (size_t)row * K + c * 8);
        }
    };

#pragma unroll
    for (int s = 0; s < NSTG - 1; s++) { load_stage(s, s); cp_commit(); }

    float d[4][8][4];
#pragma unroll
    for (int i = 0; i < 4; i++)
#pragma unroll
        for (int j = 0; j < 8; j++)
#pragma unroll
            for (int c = 0; c < 4; c++) d[i][j][c] = 0.f;

    for (int kt = 0; kt < KT; kt++) {
        cp_wait<NSTG - 2>();
        __syncthreads();

        const int nk = kt + NSTG - 1;
        if (nk < KT) load_stage(nk, nk % NSTG);
        cp_commit();

        const uint32_t sA_u = smem_base + (uint32_t)((kt % NSTG) * STG_BYTES);
        const uint32_t sB_u = sA_u + A_BYTES;

#pragma unroll
        for (int ks = 0; ks < 4; ks++) {
            const int ko = ks * 16;
            uint32_t a[4][4], b[8][2];
#pragma unroll
            for (int i = 0; i < 4; i++) {
                uint32_t addr = sA_u +
                    (uint32_t)((wm + i * 16 + a_row) * SROW + ko + a_col) * 2;
                ldsm_x4(a[i][0], a[i][1], a[i][2], a[i][3], addr);
            }
#pragma unroll
            for (int jj = 0; jj < 4; jj++) {
                uint32_t addr = sB_u +
                    (uint32_t)((wn + jj * 16 + b_row) * SROW + ko + b_col) * 2;
                ldsm_x4(b[2 * jj][0], b[2 * jj][1],
                        b[2 * jj + 1][0], b[2 * jj + 1][1], addr);
            }
#pragma unroll
            for (int i = 0; i < 4; i++)
#pragma unroll
                for (int j = 0; j < 8; j++)
                    mma16816(d[i][j], a[i], b[j]);
        }
    }

    if (MODE == 0) {
        __half* C = (__half*)Cv;
#pragma unroll
        for (int i = 0; i < 4; i++) {
#pragma unroll
            for (int j = 0; j < 8; j++) {
                int col = n0 + wn + j * 8 + tg * 2;
                float s0 = vec[col], s1 = vec[col + 1];
                int r0 = m0 + wm + i * 16 + g;
                *(__half2*)(C + (size_t)r0 * N + col) =
                    __floats2half2_rn(d[i][j][0] * s0, d[i][j][1] * s1);
                *(__half2*)(C + (size_t)(r0 + 8) * N + col) =
                    __floats2half2_rn(d[i][j][2] * s0, d[i][j][3] * s1);
            }
        }
    } else {
        float* C = (float*)Cv;
#pragma unroll
        for (int i = 0; i < 4; i++) {
#pragma unroll
            for (int j = 0; j < 8; j++) {
                int col = n0 + wn + j * 8 + tg * 2;
                float b0 = vec[col], b1 = vec[col + 1];
                int r0 = m0 + wm + i * 16 + g;
                *(float2*)(C + (size_t)r0 * N + col) =
                    make_float2(d[i][j][0] * us + b0, d[i][j][1] * us + b1);
                *(float2*)(C + (size_t)(r0 + 8) * N + col) =
                    make_float2(d[i][j][2] * us + b0, d[i][j][3] * us + b1);
            }
        }
    }
}

// --------------------------- fused kernel -----------------------------------
// bids [0, 256): x-convert (4 per m-block, m-major).
// bids [256, 768): GEMM1 tiles (m-major), gated on xflags[mb]==4.
// bids [768, 2816): GEMM2 tiles (m-major), gated on flags[mb]==8.
__global__ void __launch_bounds__(128, 2)
fused_gemm(const float* __restrict__ x, float* __restrict__ out,
           const float* __restrict__ uscale, const float* __restrict__ bias) {
    extern __shared__ char smc[];
    const int bid = blockIdx.x;

    if (bid < XC_TILES) {
        // convert 32 rows of x to fp16
        const int mb = bid >> 2, q = bid & 3;
        const size_t base = ((size_t)mb * TM + q * 32) * IN_F;
        const float* src = x + base;
        __half* dst = g_x16 + base;
        const int total = 32 * IN_F / 4;            // 32768 float4 chunks
        for (int i = threadIdx.x; i < total; i += 128) {
            float4 v = *(const float4*)(src + (size_t)i * 4);
            *(__half2*)(dst + (size_t)i * 4)     = __floats2half2_rn(v.x, v.y);
            *(__half2*)(dst + (size_t)i * 4 + 2) = __floats2half2_rn(v.z, v.w);
        }
        __threadfence();
        __syncthreads();
        if (threadIdx.x == 0) atomicAdd(&g_xflags[mb], 1);
    } else if (bid < XC_TILES + G1_TILES) {
        const int b1 = bid - XC_TILES;
        const int mb = b1 >> 3;                     // 8 n-tiles per m-block
        const int n0 = (b1 & 7) * TN;
        if (threadIdx.x == 0) {
            while (ld_acquire_gpu(&g_xflags[mb]) < XC_PER_MB) { }
        }
        __syncthreads();
        gemm_body<0>(g_x16, g_W1, g_H, RANK, IN_F, g_hscale, 0.f,
                     mb * TM, n0, smc);
        __threadfence();
        __syncthreads();
        if (threadIdx.x == 0) atomicAdd(&g_flags[mb], 1);
    } else {
        const int b2 = bid - XC_TILES - G1_TILES;
        const int mb = b2 >> 5;                     // 32 n-tiles per m-block
        const int n0 = (b2 & 31) * TN;
        if (threadIdx.x == 0) {
            while (ld_acquire_gpu(&g_flags[mb]) < G1_TN_TILES) { }
        }
        __syncthreads();
        const float us = __ldg(uscale);
        gemm_body<1>(g_H, g_W2, out, OUT_F, RANK, bias, us,
                     mb * TM, n0, smc);
    }
}

// ------------------------------ launch -------------------------------------
extern "C" void kernel_launch(void* const* d_in, const int* in_sizes, int n_in,
                              void* d_out, int out_size) {
    const float* x        = (const float*)d_in[0];
    const int*   U_data   = (const int*)  d_in[1];
    const float* U_scale  = (const float*)d_in[2];
    const float* U_zp     = (const float*)d_in[3];
    const int*   S_data   = (const int*)  d_in[4];
    const float* S_scale  = (const float*)d_in[5];
    const float* S_zp     = (const float*)d_in[6];
    const int*   Vh_data  = (const int*)  d_in[7];
    const float* Vh_scale = (const float*)d_in[8];
    const float* Vh_zp    = (const float*)d_in[9];
    const float* bias     = (const float*)d_in[10];
    float* out = (float*)d_out;
    (void)in_sizes; (void)n_in; (void)out_size;

    cudaFuncSetAttribute(fused_gemm, cudaFuncAttributeMaxDynamicSharedMemorySize,
                         SMEM_USE);

    // prep: weights, hscale, flag resets (~10us, fully parallel)
    {
        size_t total = NW1_CH + NW2_CH + RANK + 2 * MBLKS;
        prep_all<<<(unsigned)((total + 255) / 256), 256>>>(
            Vh_data, Vh_zp, U_data, U_zp, S_data, S_scale, S_zp, Vh_scale);
    }
    // fused x-convert + GEMM1 + GEMM2 (flag-based cross-tile dependencies)
    fused_gemm<<<XC_TILES + G1_TILES + G2_TILES, 128, SMEM_USE>>>(
        x, out, U_scale, bias);
}

// round 14
// speedup vs baseline: 1.1645x; 1.1645x over previous
#include <cuda_runtime.h>
#include <cuda_fp16.h>
#include <cstdint>

// ---------------------------------------------------------------------------
// CompressedLinear: y = ((x @ Vh^T) * S) @ U^T + bias
// mma.sync fp16 path. R13 lesson: keep memory-bound prep at high occupancy
// (own kernel); R11 base restored. This round's one change: NSTG 3->2 so
// smem = 73728B/CTA -> 3 CTAs/SM (12 warps/SM), launch_bounds(128,3).
// Mainloop otherwise identical to R11 (64x64 warp tiles, all-LDSM).
// ---------------------------------------------------------------------------

#define M_TOK   8192
#define IN_F    4096
#define OUT_F   4096
#define RANK    1024

#define TM      128
#define TN      128
#define G1_TN_TILES (RANK / TN)                    // 8
#define G1_TILES    ((M_TOK / TM) * G1_TN_TILES)   // 512
#define G2_TN_TILES (OUT_F / TN)                   // 32
#define G2_TILES    ((M_TOK / TM) * G2_TN_TILES)   // 2048
#define MBLKS       (M_TOK / TM)                   // 64

__device__ __half g_x16[(size_t)M_TOK * IN_F];   // 64 MB (fp16 x)
__device__ __half g_W1[(size_t)RANK * IN_F];     // 8 MB  (Vh - 128)
__device__ __half g_W2[(size_t)OUT_F * RANK];    // 8 MB  (U - 128)
__device__ __half g_H [(size_t)M_TOK * RANK];    // 16 MB (h * hscale)
__device__ float  g_hscale[RANK];
__device__ int    g_flags[MBLKS];

// ------------------------- merged prep kernel ------------------------------
#define NX_CH   ((size_t)M_TOK * IN_F / 4)       // 8,388,608 chunks
#define NW1_CH  ((size_t)RANK * IN_F / 4)        // 1,048,576
#define NW2_CH  ((size_t)OUT_F * RANK / 4)       // 1,048,576

__global__ void prep_all(const float* __restrict__ x,
                         const int* __restrict__ Vh_data, const float* __restrict__ Vh_zp,
                         const int* __restrict__ U_data,  const float* __restrict__ U_zp,
                         const int* __restrict__ S_data,  const float* __restrict__ S_scale,
                         const float* __restrict__ S_zp,  const float* __restrict__ Vh_scale) {
    size_t g = (size_t)blockIdx.x * blockDim.x + threadIdx.x;
    if (g < NX_CH) {
        size_t i = g * 4;
        float4 v = *(const float4*)(x + i);
        *(__half2*)(g_x16 + i)     = __floats2half2_rn(v.x, v.y);
        *(__half2*)(g_x16 + i + 2) = __floats2half2_rn(v.z, v.w);
    } else if (g < NX_CH + NW1_CH) {
        size_t i = (g - NX_CH) * 4;
        float z = *Vh_zp;
        int4 d = *(const int4*)(Vh_data + i);
        *(__half2*)(g_W1 + i)     = __floats2half2_rn((float)d.x - z, (float)d.y - z);
        *(__half2*)(g_W1 + i + 2) = __floats2half2_rn((float)d.z - z, (float)d.w - z);
    } else if (g < NX_CH + NW1_CH + NW2_CH) {
        size_t i = (g - NX_CH - NW1_CH) * 4;
        float z = *U_zp;
        int4 d = *(const int4*)(U_data + i);
        *(__half2*)(g_W2 + i)     = __floats2half2_rn((float)d.x - z, (float)d.y - z);
        *(__half2*)(g_W2 + i + 2) = __floats2half2_rn((float)d.z - z, (float)d.w - z);
    } else if (g < NX_CH + NW1_CH + NW2_CH + RANK) {
        int r = (int)(g - NX_CH - NW1_CH - NW2_CH);
        g_hscale[r] = Vh_scale[0] * S_scale[0] * ((float)S_data[r] - S_zp[0]);
    } else if (g < NX_CH + NW1_CH + NW2_CH + RANK + MBLKS) {
        g_flags[g - NX_CH - NW1_CH - NW2_CH - RANK] = 0;
    }
}

// ---------------------------- PTX helpers ----------------------------------
__device__ __forceinline__ void cp_async16(uint32_t saddr, const void* gp) {
    asm volatile("cp.async.cg.shared.global [%0], [%1], 16;\n" :: "r"(saddr), "l"(gp));
}
__device__ __forceinline__ void cp_commit() { asm volatile("cp.async.commit_group;\n"); }
template<int N> __device__ __forceinline__ void cp_wait() {
    asm volatile("cp.async.wait_group %0;\n" :: "n"(N));
}
__device__ __forceinline__ void mma16816(float* d, const uint32_t* a, const uint32_t* b) {
    asm volatile(
        "mma.sync.aligned.m16n8k16.row.col.f32.f16.f16.f32 "
        "{%0,%1,%2,%3}, {%4,%5,%6,%7}, {%8,%9}, {%0,%1,%2,%3};\n"
        : "+f"(d[0]), "+f"(d[1]), "+f"(d[2]), "+f"(d[3])
        : "r"(a[0]), "r"(a[1]), "r"(a[2]), "r"(a[3]), "r"(b[0]), "r"(b[1]));
}
__device__ __forceinline__ int ld_acquire_gpu(const int* p) {
    int v;
    asm volatile("ld.acquire.gpu.s32 %0, [%1];" : "=r"(v) : "l"(p) : "memory");
    return v;
}
__device__ __forceinline__ void ldsm_x4(uint32_t& r0, uint32_t& r1,
                                        uint32_t& r2, uint32_t& r3, uint32_t saddr) {
    asm volatile("ldmatrix.sync.aligned.m8n8.x4.shared.b16 {%0,%1,%2,%3}, [%4];"
                 : "=r"(r0), "=r"(r1), "=r"(r2), "=r"(r3) : "r"(saddr));
}

// ----------------------------- GEMM body -----------------------------------
#define BKH     64
#define NSTG    2
#define SROW    72
#define A_BYTES (TM * SROW * 2)             // 18432
#define B_BYTES (TN * SROW * 2)             // 18432
#define STG_BYTES (A_BYTES + B_BYTES)       // 36864
#define SMEM_USE (NSTG * STG_BYTES)         // 73728 -> 3 CTAs/SM

// MODE 0 (GEMM1): C half, *= vec[col].  MODE 1 (GEMM2): C float, *us + vec.
// 4 warps, warp grid 2x2: warp tile 64x64. All fp16, all LDSM.
template<int MODE>
__device__ __forceinline__ void
gemm_body(const __half* __restrict__ A, const __half* __restrict__ B,
          void* __restrict__ Cv, int N, int K,
          const float* __restrict__ vec, float us,
          int m0, int n0, char* smc) {
    const uint32_t smem_base = (uint32_t)__cvta_generic_to_shared(smc);

    const int tid  = threadIdx.x;
    const int warp = tid >> 5;
    const int lane = tid & 31;
    const int wm = (warp >> 1) * 64;        // 0 / 64
    const int wn = (warp & 1) * 64;         // 0 / 64
    const int g  = lane >> 2;
    const int tg = lane & 3;
    const int KT = K / BKH;

    const int a_row = (lane & 15);
    const int a_col = (lane >> 4) << 3;
    const int b_row = ((lane >> 4) << 3) + (lane & 7);
    const int b_col = ((lane >> 3) & 1) << 3;

    auto load_stage = [&](int kt, int s) {
        const uint32_t tA = smem_base + (uint32_t)(s * STG_BYTES);
        const uint32_t tB = tA + A_BYTES;
        const __half* gA = A + (size_t)m0 * K + (size_t)kt * BKH;
        const __half* gB = B + (size_t)n0 * K + (size_t)kt * BKH;
#pragma unroll
        for (int r = 0; r < 8; r++) {               // 1024 chunks: 128 rows x 8
            int i = tid + r * 128;
            int row = i >> 3, c = i & 7;
            cp_async16(tA + (uint32_t)(row * SROW + c * 8) * 2,
                       gA + (size_t)row * K + c * 8);
        }
#pragma unroll
        for (int r = 0; r < 8; r++) {
            int i = tid + r * 128;
            int row = i >> 3, c = i & 7;
            cp_async16(tB + (uint32_t)(row * SROW + c * 8) * 2,
                       gB + (size_t)row * K + c * 8);
        }
    };

#pragma unroll
    for (int s = 0; s < NSTG - 1; s++) { load_stage(s, s); cp_commit(); }

    float d[4][8][4];
#pragma unroll
    for (int i = 0; i < 4; i++)
#pragma unroll
        for (int j = 0; j < 8; j++)
#pragma unroll
            for (int c = 0; c < 4; c++) d[i][j][c] = 0.f;

    for (int kt = 0; kt < KT; kt++) {
        cp_wait<NSTG - 2>();
        __syncthreads();

        const int nk = kt + NSTG - 1;
        if (nk < KT) load_stage(nk, nk % NSTG);
        cp_commit();

        const uint32_t sA_u = smem_base + (uint32_t)((kt % NSTG) * STG_BYTES);
        const uint32_t sB_u = sA_u + A_BYTES;

#pragma unroll
        for (int ks = 0; ks < 4; ks++) {
            const int ko = ks * 16;
            uint32_t a[4][4], b[8][2];
#pragma unroll
            for (int i = 0; i < 4; i++) {
                uint32_t addr = sA_u +
                    (uint32_t)((wm + i * 16 + a_row) * SROW + ko + a_col) * 2;
                ldsm_x4(a[i][0], a[i][1], a[i][2], a[i][3], addr);
            }
#pragma unroll
            for (int jj = 0; jj < 4; jj++) {
                uint32_t addr = sB_u +
                    (uint32_t)((wn + jj * 16 + b_row) * SROW + ko + b_col) * 2;
                ldsm_x4(b[2 * jj][0], b[2 * jj][1],
                        b[2 * jj + 1][0], b[2 * jj + 1][1], addr);
            }
#pragma unroll
            for (int i = 0; i < 4; i++)
#pragma unroll
                for (int j = 0; j < 8; j++)
                    mma16816(d[i][j], a[i], b[j]);
        }
    }

    if (MODE == 0) {
        __half* C = (__half*)Cv;
#pragma unroll
        for (int i = 0; i < 4; i++) {
#pragma unroll
            for (int j = 0; j < 8; j++) {
                int col = n0 + wn + j * 8 + tg * 2;
                float s0 = vec[col], s1 = vec[col + 1];
                int r0 = m0 + wm + i * 16 + g;
                *(__half2*)(C + (size_t)r0 * N + col) =
                    __floats2half2_rn(d[i][j][0] * s0, d[i][j][1] * s1);
                *(__half2*)(C + (size_t)(r0 + 8) * N + col) =
                    __floats2half2_rn(d[i][j][2] * s0, d[i][j][3] * s1);
            }
        }
    } else {
        float* C = (float*)Cv;
#pragma unroll
        for (int i = 0; i < 4; i++) {
#pragma unroll
            for (int j = 0; j < 8; j++) {
                int col = n0 + wn + j * 8 + tg * 2;
                float b0 = vec[col], b1 = vec[col + 1];
                int r0 = m0 + wm + i * 16 + g;
                *(float2*)(C + (size_t)r0 * N + col) =
                    make_float2(d[i][j][0] * us + b0, d[i][j][1] * us + b1);
                *(float2*)(C + (size_t)(r0 + 8) * N + col) =
                    make_float2(d[i][j][2] * us + b0, d[i][j][3] * us + b1);
            }
        }
    }
}

// --------------------------- fused GEMM kernel ------------------------------
// bids [0, 512): GEMM1 tiles (m-major). bids [512, 2560): GEMM2 tiles (m-major).
__global__ void __launch_bounds__(128, 3)
fused_gemm(float* __restrict__ out,
           const float* __restrict__ uscale, const float* __restrict__ bias) {
    extern __shared__ char smc[];
    const int bid = blockIdx.x;

    if (bid < G1_TILES) {
        const int mb = bid >> 3;             // 8 n-tiles per m-block
        const int n0 = (bid & 7) * TN;
        gemm_body<0>(g_x16, g_W1, g_H, RANK, IN_F, g_hscale, 0.f,
                     mb * TM, n0, smc);
        __threadfence();
        __syncthreads();
        if (threadIdx.x == 0) atomicAdd(&g_flags[mb], 1);
    } else {
        const int b2 = bid - G1_TILES;
        const int mb = b2 >> 5;              // 32 n-tiles per m-block
        const int n0 = (b2 & 31) * TN;
        if (threadIdx.x == 0) {
            while (ld_acquire_gpu(&g_flags[mb]) < G1_TN_TILES) { }
        }
        __syncthreads();
        const float us = __ldg(uscale);
        gemm_body<1>(g_H, g_W2, out, OUT_F, RANK, bias, us,
                     mb * TM, n0, smc);
    }
}

// ------------------------------ launch -------------------------------------
extern "C" void kernel_launch(void* const* d_in, const int* in_sizes, int n_in,
                              void* d_out, int out_size) {
    const float* x        = (const float*)d_in[0];
    const int*   U_data   = (const int*)  d_in[1];
    const float* U_scale  = (const float*)d_in[2];
    const float* U_zp     = (const float*)d_in[3];
    const int*   S_data   = (const int*)  d_in[4];
    const float* S_scale  = (const float*)d_in[5];
    const float* S_zp     = (const float*)d_in[6];
    const int*   Vh_data  = (const int*)  d_in[7];
    const float* Vh_scale = (const float*)d_in[8];
    const float* Vh_zp    = (const float*)d_in[9];
    const float* bias     = (const float*)d_in[10];
    float* out = (float*)d_out;
    (void)in_sizes; (void)n_in; (void)out_size;

    cudaFuncSetAttribute(fused_gemm, cudaFuncAttributeMaxDynamicSharedMemorySize,
                         SMEM_USE);

    // prep: x->fp16, W1, W2, hscale, flag reset (one launch, high occupancy)
    {
        size_t total = NX_CH + NW1_CH + NW2_CH + RANK + MBLKS;
        prep_all<<<(unsigned)((total + 255) / 256), 256>>>(
            x, Vh_data, Vh_zp, U_data, U_zp, S_data, S_scale, S_zp, Vh_scale);
    }
    // fused GEMM1 + GEMM2 (flag-based cross-tile dependency)
    fused_gemm<<<G1_TILES + G2_TILES, 128, SMEM_USE>>>(out, U_scale, bias);
}

// round 15
// speedup vs baseline: 1.6236x; 1.3943x over previous
#include <cuda_runtime.h>
#include <cuda_fp16.h>
#include <cstdint>

// ---------------------------------------------------------------------------
// CompressedLinear: y = ((x @ Vh^T) * S) @ U^T + bias
// mma.sync fp16 path. R12/R14 exhausted the occupancy ladder (8-warp: LDS up;
// 3 CTA: spills). R11 config is the plateau. This round: double-buffered
// fragment pipeline in the ks loop (prefetch frags ks+1 during MMAs of ks)
// to hide LDSM->MMA latency within each warp. Everything else = R11.
// ---------------------------------------------------------------------------

#define M_TOK   8192
#define IN_F    4096
#define OUT_F   4096
#define RANK    1024

#define TM      128
#define TN      128
#define G1_TN_TILES (RANK / TN)                    // 8
#define G1_TILES    ((M_TOK / TM) * G1_TN_TILES)   // 512
#define G2_TN_TILES (OUT_F / TN)                   // 32
#define G2_TILES    ((M_TOK / TM) * G2_TN_TILES)   // 2048
#define MBLKS       (M_TOK / TM)                   // 64

__device__ __half g_x16[(size_t)M_TOK * IN_F];   // 64 MB (fp16 x)
__device__ __half g_W1[(size_t)RANK * IN_F];     // 8 MB  (Vh - 128)
__device__ __half g_W2[(size_t)OUT_F * RANK];    // 8 MB  (U - 128)
__device__ __half g_H [(size_t)M_TOK * RANK];    // 16 MB (h * hscale)
__device__ float  g_hscale[RANK];
__device__ int    g_flags[MBLKS];

// ------------------------- merged prep kernel ------------------------------
#define NX_CH   ((size_t)M_TOK * IN_F / 4)       // 8,388,608 chunks
#define NW1_CH  ((size_t)RANK * IN_F / 4)        // 1,048,576
#define NW2_CH  ((size_t)OUT_F * RANK / 4)       // 1,048,576

__global__ void prep_all(const float* __restrict__ x,
                         const int* __restrict__ Vh_data, const float* __restrict__ Vh_zp,
                         const int* __restrict__ U_data,  const float* __restrict__ U_zp,
                         const int* __restrict__ S_data,  const float* __restrict__ S_scale,
                         const float* __restrict__ S_zp,  const float* __restrict__ Vh_scale) {
    size_t g = (size_t)blockIdx.x * blockDim.x + threadIdx.x;
    if (g < NX_CH) {
        size_t i = g * 4;
        float4 v = *(const float4*)(x + i);
        *(__half2*)(g_x16 + i)     = __floats2half2_rn(v.x, v.y);
        *(__half2*)(g_x16 + i + 2) = __floats2half2_rn(v.z, v.w);
    } else if (g < NX_CH + NW1_CH) {
        size_t i = (g - NX_CH) * 4;
        float z = *Vh_zp;
        int4 d = *(const int4*)(Vh_data + i);
        *(__half2*)(g_W1 + i)     = __floats2half2_rn((float)d.x - z, (float)d.y - z);
        *(__half2*)(g_W1 + i + 2) = __floats2half2_rn((float)d.z - z, (float)d.w - z);
    } else if (g < NX_CH + NW1_CH + NW2_CH) {
        size_t i = (g - NX_CH - NW1_CH) * 4;
        float z = *U_zp;
        int4 d = *(const int4*)(U_data + i);
        *(__half2*)(g_W2 + i)     = __floats2half2_rn((float)d.x - z, (float)d.y - z);
        *(__half2*)(g_W2 + i + 2) = __floats2half2_rn((float)d.z - z, (float)d.w - z);
    } else if (g < NX_CH + NW1_CH + NW2_CH + RANK) {
        int r = (int)(g - NX_CH - NW1_CH - NW2_CH);
        g_hscale[r] = Vh_scale[0] * S_scale[0] * ((float)S_data[r] - S_zp[0]);
    } else if (g < NX_CH + NW1_CH + NW2_CH + RANK + MBLKS) {
        g_flags[g - NX_CH - NW1_CH - NW2_CH - RANK] = 0;
    }
}

// ---------------------------- PTX helpers ----------------------------------
__device__ __forceinline__ void cp_async16(uint32_t saddr, const void* gp) {
    asm volatile("cp.async.cg.shared.global [%0], [%1], 16;\n" :: "r"(saddr), "l"(gp));
}
__device__ __forceinline__ void cp_commit() { asm volatile("cp.async.commit_group;\n"); }
template<int N> __device__ __forceinline__ void cp_wait() {
    asm volatile("cp.async.wait_group %0;\n" :: "n"(N));
}
__device__ __forceinline__ void mma16816(float* d, const uint32_t* a, const uint32_t* b) {
    asm volatile(
        "mma.sync.aligned.m16n8k16.row.col.f32.f16.f16.f32 "
        "{%0,%1,%2,%3}, {%4,%5,%6,%7}, {%8,%9}, {%0,%1,%2,%3};\n"
        : "+f"(d[0]), "+f"(d[1]), "+f"(d[2]), "+f"(d[3])
        : "r"(a[0]), "r"(a[1]), "r"(a[2]), "r"(a[3]), "r"(b[0]), "r"(b[1]));
}
__device__ __forceinline__ int ld_acquire_gpu(const int* p) {
    int v;
    asm volatile("ld.acquire.gpu.s32 %0, [%1];" : "=r"(v) : "l"(p) : "memory");
    return v;
}
__device__ __forceinline__ void ldsm_x4(uint32_t& r0, uint32_t& r1,
                                        uint32_t& r2, uint32_t& r3, uint32_t saddr) {
    asm volatile("ldmatrix.sync.aligned.m8n8.x4.shared.b16 {%0,%1,%2,%3}, [%4];"
                 : "=r"(r0), "=r"(r1), "=r"(r2), "=r"(r3) : "r"(saddr));
}

// ----------------------------- GEMM body -----------------------------------
#define BKH     64
#define NSTG    3
#define SROW    72
#define A_BYTES (TM * SROW * 2)             // 18432
#define B_BYTES (TN * SROW * 2)             // 18432
#define STG_BYTES (A_BYTES + B_BYTES)       // 36864
#define SMEM_USE (NSTG * STG_BYTES)         // 110592 -> 2 CTAs/SM

// MODE 0 (GEMM1): C half, *= vec[col].  MODE 1 (GEMM2): C float, *us + vec.
// 4 warps, warp grid 2x2: warp tile 64x64. All LDSM, double-buffered frags.
template<int MODE>
__device__ __forceinline__ void
gemm_body(const __half* __restrict__ A, const __half* __restrict__ B,
          void* __restrict__ Cv, int N, int K,
          const float* __restrict__ vec, float us,
          int m0, int n0, char* smc) {
    const uint32_t smem_base = (uint32_t)__cvta_generic_to_shared(smc);

    const int tid  = threadIdx.x;
    const int warp = tid >> 5;
    const int lane = tid & 31;
    const int wm = (warp >> 1) * 64;        // 0 / 64
    const int wn = (warp & 1) * 64;         // 0 / 64
    const int g  = lane >> 2;
    const int tg = lane & 3;
    const int KT = K / BKH;

    const int a_row = (lane & 15);
    const int a_col = (lane >> 4) << 3;
    const int b_row = ((lane >> 4) << 3) + (lane & 7);
    const int b_col = ((lane >> 3) & 1) << 3;

    auto load_stage = [&](int kt, int s) {
        const uint32_t tA = smem_base + (uint32_t)(s * STG_BYTES);
        const uint32_t tB = tA + A_BYTES;
        const __half* gA = A + (size_t)m0 * K + (size_t)kt * BKH;
        const __half* gB = B + (size_t)n0 * K + (size_t)kt * BKH;
#pragma unroll
        for (int r = 0; r < 8; r++) {               // 1024 chunks: 128 rows x 8
            int i = tid + r * 128;
            int row = i >> 3, c = i & 7;
            cp_async16(tA + (uint32_t)(row * SROW + c * 8) * 2,
                       gA + (size_t)row * K + c * 8);
        }
#pragma unroll
        for (int r = 0; r < 8; r++) {
            int i = tid + r * 128;
            int row = i >> 3, c = i & 7;
            cp_async16(tB + (uint32_t)(row * SROW + c * 8) * 2,
                       gB + (size_t)row * K + c * 8);
        }
    };

#pragma unroll
    for (int s = 0; s < NSTG - 1; s++) { load_stage(s, s); cp_commit(); }

    float d[4][8][4];
#pragma unroll
    for (int i = 0; i < 4; i++)
#pragma unroll
        for (int j = 0; j < 8; j++)
#pragma unroll
            for (int c = 0; c < 4; c++) d[i][j][c] = 0.f;

    uint32_t a[2][4][4], b[2][8][2];        // double-buffered fragments

    for (int kt = 0; kt < KT; kt++) {
        cp_wait<NSTG - 2>();
        __syncthreads();

        const int nk = kt + NSTG - 1;
        if (nk < KT) load_stage(nk, nk % NSTG);
        cp_commit();

        const uint32_t sA_u = smem_base + (uint32_t)((kt % NSTG) * STG_BYTES);
        const uint32_t sB_u = sA_u + A_BYTES;

        // frag loader for one ks step into buffer p
        auto load_frags = [&](int ks, int p) {
            const int ko = ks * 16;
#pragma unroll
            for (int i = 0; i < 4; i++) {
                uint32_t addr = sA_u +
                    (uint32_t)((wm + i * 16 + a_row) * SROW + ko + a_col) * 2;
                ldsm_x4(a[p][i][0], a[p][i][1], a[p][i][2], a[p][i][3], addr);
            }
#pragma unroll
            for (int jj = 0; jj < 4; jj++) {
                uint32_t addr = sB_u +
                    (uint32_t)((wn + jj * 16 + b_row) * SROW + ko + b_col) * 2;
                ldsm_x4(b[p][2 * jj][0], b[p][2 * jj][1],
                        b[p][2 * jj + 1][0], b[p][2 * jj + 1][1], addr);
            }
        };

        load_frags(0, 0);
#pragma unroll
        for (int ks = 0; ks < 4; ks++) {
            const int cur = ks & 1;
            if (ks < 3) load_frags(ks + 1, cur ^ 1);   // prefetch next frags
#pragma unroll
            for (int i = 0; i < 4; i++)
#pragma unroll
                for (int j = 0; j < 8; j++)
                    mma16816(d[i][j], a[cur][i], b[cur][j]);
        }
    }

    if (MODE == 0) {
        __half* C = (__half*)Cv;
#pragma unroll
        for (int i = 0; i < 4; i++) {
#pragma unroll
            for (int j = 0; j < 8; j++) {
                int col = n0 + wn + j * 8 + tg * 2;
                float s0 = vec[col], s1 = vec[col + 1];
                int r0 = m0 + wm + i * 16 + g;
                *(__half2*)(C + (size_t)r0 * N + col) =
                    __floats2half2_rn(d[i][j][0] * s0, d[i][j][1] * s1);
                *(__half2*)(C + (size_t)(r0 + 8) * N + col) =
                    __floats2half2_rn(d[i][j][2] * s0, d[i][j][3] * s1);
            }
        }
    } else {
        float* C = (float*)Cv;
#pragma unroll
        for (int i = 0; i < 4; i++) {
#pragma unroll
            for (int j = 0; j < 8; j++) {
                int col = n0 + wn + j * 8 + tg * 2;
                float b0 = vec[col], b1 = vec[col + 1];
                int r0 = m0 + wm + i * 16 + g;
                *(float2*)(C + (size_t)r0 * N + col) =
                    make_float2(d[i][j][0] * us + b0, d[i][j][1] * us + b1);
                *(float2*)(C + (size_t)(r0 + 8) * N + col) =
                    make_float2(d[i][j][2] * us + b0, d[i][j][3] * us + b1);
            }
        }
    }
}

// --------------------------- fused GEMM kernel ------------------------------
// bids [0, 512): GEMM1 tiles (m-major). bids [512, 2560): GEMM2 tiles (m-major).
__global__ void __launch_bounds__(128, 2)
fused_gemm(float* __restrict__ out,
           const float* __restrict__ uscale, const float* __restrict__ bias) {
    extern __shared__ char smc[];
    const int bid = blockIdx.x;

    if (bid < G1_TILES) {
        const int mb = bid >> 3;             // 8 n-tiles per m-block
        const int n0 = (bid & 7) * TN;
        gemm_body<0>(g_x16, g_W1, g_H, RANK, IN_F, g_hscale, 0.f,
                     mb * TM, n0, smc);
        __threadfence();
        __syncthreads();
        if (threadIdx.x == 0) atomicAdd(&g_flags[mb], 1);
    } else {
        const int b2 = bid - G1_TILES;
        const int mb = b2 >> 5;              // 32 n-tiles per m-block
        const int n0 = (b2 & 31) * TN;
        if (threadIdx.x == 0) {
            while (ld_acquire_gpu(&g_flags[mb]) < G1_TN_TILES) { }
        }
        __syncthreads();
        const float us = __ldg(uscale);
        gemm_body<1>(g_H, g_W2, out, OUT_F, RANK, bias, us,
                     mb * TM, n0, smc);
    }
}

// ------------------------------ launch -------------------------------------
extern "C" void kernel_launch(void* const* d_in, const int* in_sizes, int n_in,
                              void* d_out, int out_size) {
    const float* x        = (const float*)d_in[0];
    const int*   U_data   = (const int*)  d_in[1];
    const float* U_scale  = (const float*)d_in[2];
    const float* U_zp     = (const float*)d_in[3];
    const int*   S_data   = (const int*)  d_in[4];
    const float* S_scale  = (const float*)d_in[5];
    const float* S_zp     = (const float*)d_in[6];
    const int*   Vh_data  = (const int*)  d_in[7];
    const float* Vh_scale = (const float*)d_in[8];
    const float* Vh_zp    = (const float*)d_in[9];
    const float* bias     = (const float*)d_in[10];
    float* out = (float*)d_out;
    (void)in_sizes; (void)n_in; (void)out_size;

    cudaFuncSetAttribute(fused_gemm, cudaFuncAttributeMaxDynamicSharedMemorySize,
                         SMEM_USE);

    // prep: x->fp16, W1, W2, hscale, flag reset (one launch, high occupancy)
    {
        size_t total = NX_CH + NW1_CH + NW2_CH + RANK + MBLKS;
        prep_all<<<(unsigned)((total + 255) / 256), 256>>>(
            x, Vh_data, Vh_zp, U_data, U_zp, S_data, S_scale, S_zp, Vh_scale);
    }
    // fused GEMM1 + GEMM2 (flag-based cross-tile dependency)
    fused_gemm<<<G1_TILES + G2_TILES, 128, SMEM_USE>>>(out, U_scale, bias);
}

// round 16
// speedup vs baseline: 1.7819x; 1.0975x over previous
#include <cuda_runtime.h>
#include <cuda_fp16.h>
#include <cstdint>

// ---------------------------------------------------------------------------
// CompressedLinear: y = ((x @ Vh^T) * S) @ U^T + bias
// mma.sync fp16 path. R15 neutral -> LDSM latency not the limiter; remaining
// exposure is the kt-boundary (cp_wait + syncthreads phase-locked across the
// 2 co-resident CTAs). This round: split-barrier pipeline — mbarrier arrive /
// wait with the last ks-step of the previous stage held in registers and
// executed INSIDE the barrier window. Otherwise identical to R11.
// ---------------------------------------------------------------------------

#define M_TOK   8192
#define IN_F    4096
#define OUT_F   4096
#define RANK    1024

#define TM      128
#define TN      128
#define G1_TN_TILES (RANK / TN)                    // 8
#define G1_TILES    ((M_TOK / TM) * G1_TN_TILES)   // 512
#define G2_TN_TILES (OUT_F / TN)                   // 32
#define G2_TILES    ((M_TOK / TM) * G2_TN_TILES)   // 2048
#define MBLKS       (M_TOK / TM)                   // 64

__device__ __half g_x16[(size_t)M_TOK * IN_F];   // 64 MB (fp16 x)
__device__ __half g_W1[(size_t)RANK * IN_F];     // 8 MB  (Vh - 128)
__device__ __half g_W2[(size_t)OUT_F * RANK];    // 8 MB  (U - 128)
__device__ __half g_H [(size_t)M_TOK * RANK];    // 16 MB (h * hscale)
__device__ float  g_hscale[RANK];
__device__ int    g_flags[MBLKS];

// ------------------------- merged prep kernel ------------------------------
#define NX_CH   ((size_t)M_TOK * IN_F / 4)       // 8,388,608 chunks
#define NW1_CH  ((size_t)RANK * IN_F / 4)        // 1,048,576
#define NW2_CH  ((size_t)OUT_F * RANK / 4)       // 1,048,576

__global__ void prep_all(const float* __restrict__ x,
                         const int* __restrict__ Vh_data, const float* __restrict__ Vh_zp,
                         const int* __restrict__ U_data,  const float* __restrict__ U_zp,
                         const int* __restrict__ S_data,  const float* __restrict__ S_scale,
                         const float* __restrict__ S_zp,  const float* __restrict__ Vh_scale) {
    size_t g = (size_t)blockIdx.x * blockDim.x + threadIdx.x;
    if (g < NX_CH) {
        size_t i = g * 4;
        float4 v = *(const float4*)(x + i);
        *(__half2*)(g_x16 + i)     = __floats2half2_rn(v.x, v.y);
        *(__half2*)(g_x16 + i + 2) = __floats2half2_rn(v.z, v.w);
    } else if (g < NX_CH + NW1_CH) {
        size_t i = (g - NX_CH) * 4;
        float z = *Vh_zp;
        int4 d = *(const int4*)(Vh_data + i);
        *(__half2*)(g_W1 + i)     = __floats2half2_rn((float)d.x - z, (float)d.y - z);
        *(__half2*)(g_W1 + i + 2) = __floats2half2_rn((float)d.z - z, (float)d.w - z);
    } else if (g < NX_CH + NW1_CH + NW2_CH) {
        size_t i = (g - NX_CH - NW1_CH) * 4;
        float z = *U_zp;
        int4 d = *(const int4*)(U_data + i);
        *(__half2*)(g_W2 + i)     = __floats2half2_rn((float)d.x - z, (float)d.y - z);
        *(__half2*)(g_W2 + i + 2) = __floats2half2_rn((float)d.z - z, (float)d.w - z);
    } else if (g < NX_CH + NW1_CH + NW2_CH + RANK) {
        int r = (int)(g - NX_CH - NW1_CH - NW2_CH);
        g_hscale[r] = Vh_scale[0] * S_scale[0] * ((float)S_data[r] - S_zp[0]);
    } else if (g < NX_CH + NW1_CH + NW2_CH + RANK + MBLKS) {
        g_flags[g - NX_CH - NW1_CH - NW2_CH - RANK] = 0;
    }
}

// ---------------------------- PTX helpers ----------------------------------
__device__ __forceinline__ void cp_async16(uint32_t saddr, const void* gp) {
    asm volatile("cp.async.cg.shared.global [%0], [%1], 16;\n" :: "r"(saddr), "l"(gp));
}
__device__ __forceinline__ void cp_commit() { asm volatile("cp.async.commit_group;\n"); }
template<int N> __device__ __forceinline__ void cp_wait() {
    asm volatile("cp.async.wait_group %0;\n" :: "n"(N));
}
__device__ __forceinline__ void mma16816(float* d, const uint32_t* a, const uint32_t* b) {
    asm volatile(
        "mma.sync.aligned.m16n8k16.row.col.f32.f16.f16.f32 "
        "{%0,%1,%2,%3}, {%4,%5,%6,%7}, {%8,%9}, {%0,%1,%2,%3};\n"
        : "+f"(d[0]), "+f"(d[1]), "+f"(d[2]), "+f"(d[3])
        : "r"(a[0]), "r"(a[1]), "r"(a[2]), "r"(a[3]), "r"(b[0]), "r"(b[1]));
}
__device__ __forceinline__ int ld_acquire_gpu(const int* p) {
    int v;
    asm volatile("ld.acquire.gpu.s32 %0, [%1];" : "=r"(v) : "l"(p) : "memory");
    return v;
}
__device__ __forceinline__ void ldsm_x4(uint32_t& r0, uint32_t& r1,
                                        uint32_t& r2, uint32_t& r3, uint32_t saddr) {
    asm volatile("ldmatrix.sync.aligned.m8n8.x4.shared.b16 {%0,%1,%2,%3}, [%4];"
                 : "=r"(r0), "=r"(r1), "=r"(r2), "=r"(r3) : "r"(saddr));
}
#define MBAR_INIT(mb, cnt) \
    asm volatile("mbarrier.init.shared.b64 [%0], %1;" :: "r"(mb), "r"(cnt) : "memory")
#define MBAR_ARRIVE(mb) \
    asm volatile("mbarrier.arrive.shared.b64 _, [%0];" :: "r"(mb) : "memory")
__device__ __forceinline__ void mbar_wait(uint32_t mb, uint32_t parity) {
    uint32_t done;
    asm volatile(
        "{\n\t.reg .pred p;\n\t"
        "mbarrier.try_wait.parity.acquire.cta.shared::cta.b64 p, [%1], %2;\n\t"
        "selp.b32 %0, 1, 0, p;\n\t}"
        : "=r"(done) : "r"(mb), "r"(parity) : "memory");
    if (!done) {
        asm volatile(
            "{\n\t.reg .pred P1;\n\t"
            "W_%=:\n\t"
            "mbarrier.try_wait.parity.acquire.cta.shared::cta.b64 P1, [%0], %1, 0x989680;\n\t"
            "@P1 bra.uni D_%=;\n\t"
            "bra.uni W_%=;\n\t"
            "D_%=:\n\t}"
            :: "r"(mb), "r"(parity) : "memory");
    }
}

// ----------------------------- GEMM body -----------------------------------
#define BKH     64
#define NSTG    3
#define SROW    72
#define A_BYTES (TM * SROW * 2)             // 18432
#define B_BYTES (TN * SROW * 2)             // 18432
#define STG_BYTES (A_BYTES + B_BYTES)       // 36864
#define SMEM_USE (128 + NSTG * STG_BYTES)   // 110720 -> 2 CTAs/SM

// MODE 0 (GEMM1): C half, *= vec[col].  MODE 1 (GEMM2): C float, *us + vec.
// 4 warps, warp grid 2x2: warp tile 64x64. All LDSM. Split-barrier pipeline:
// last ks-step of stage kt-1 executes between mbarrier arrive and wait.
template<int MODE>
__device__ __forceinline__ void
gemm_body(const __half* __restrict__ A, const __half* __restrict__ B,
          void* __restrict__ Cv, int N, int K,
          const float* __restrict__ vec, float us,
          int m0, int n0, char* smc) {
    const uint32_t smem_base = (uint32_t)__cvta_generic_to_shared(smc);
    const uint32_t mbar  = smem_base;       // 8B mbarrier
    const uint32_t tile0 = smem_base + 128; // stages start here

    const int tid  = threadIdx.x;
    const int warp = tid >> 5;
    const int lane = tid & 31;
    const int wm = (warp >> 1) * 64;        // 0 / 64
    const int wn = (warp & 1) * 64;         // 0 / 64
    const int g  = lane >> 2;
    const int tg = lane & 3;
    const int KT = K / BKH;

    const int a_row = (lane & 15);
    const int a_col = (lane >> 4) << 3;
    const int b_row = ((lane >> 4) << 3) + (lane & 7);
    const int b_col = ((lane >> 3) & 1) << 3;

    if (tid == 0) MBAR_INIT(mbar, 128);
    __syncthreads();                        // once, for mbarrier init

    auto load_stage = [&](int kt, int s) {
        const uint32_t tA = tile0 + (uint32_t)(s * STG_BYTES);
        const uint32_t tB = tA + A_BYTES;
        const __half* gA = A + (size_t)m0 * K + (size_t)kt * BKH;
        const __half* gB = B + (size_t)n0 * K + (size_t)kt * BKH;
#pragma unroll
        for (int r = 0; r < 8; r++) {               // 1024 chunks: 128 rows x 8
            int i = tid + r * 128;
            int row = i >> 3, c = i & 7;
            cp_async16(tA + (uint32_t)(row * SROW + c * 8) * 2,
                       gA + (size_t)row * K + c * 8);
        }
#pragma unroll
        for (int r = 0; r < 8; r++) {
            int i = tid + r * 128;
            int row = i >> 3, c = i & 7;
            cp_async16(tB + (uint32_t)(row * SROW + c * 8) * 2,
                       gB + (size_t)row * K + c * 8);
        }
    };

#pragma unroll
    for (int s = 0; s < NSTG - 1; s++) { load_stage(s, s); cp_commit(); }

    float d[4][8][4];
#pragma unroll
    for (int i = 0; i < 4; i++)
#pragma unroll
        for (int j = 0; j < 8; j++)
#pragma unroll
            for (int c = 0; c < 4; c++) d[i][j][c] = 0.f;

    uint32_t ah[4][4], bh[8][2];            // held ks3 fragments (prev stage)

    for (int kt = 0; kt < KT; kt++) {
        cp_wait<NSTG - 2>();                // my cp.asyncs for stage kt done
        MBAR_ARRIVE(mbar);

        if (kt > 0) {                       // overlap barrier with held MMAs
#pragma unroll
            for (int i = 0; i < 4; i++)
#pragma unroll
                for (int j = 0; j < 8; j++)
                    mma16816(d[i][j], ah[i], bh[j]);
        }

        mbar_wait(mbar, (uint32_t)(kt & 1));

        const int nk = kt + NSTG - 1;
        if (nk < KT) load_stage(nk, nk % NSTG);
        cp_commit();

        const uint32_t sA_u = tile0 + (uint32_t)((kt % NSTG) * STG_BYTES);
        const uint32_t sB_u = sA_u + A_BYTES;

#pragma unroll
        for (int ks = 0; ks < 3; ks++) {
            const int ko = ks * 16;
            uint32_t a[4][4], b[8][2];
#pragma unroll
            for (int i = 0; i < 4; i++) {
                uint32_t addr = sA_u +
                    (uint32_t)((wm + i * 16 + a_row) * SROW + ko + a_col) * 2;
                ldsm_x4(a[i][0], a[i][1], a[i][2], a[i][3], addr);
            }
#pragma unroll
            for (int jj = 0; jj < 4; jj++) {
                uint32_t addr = sB_u +
                    (uint32_t)((wn + jj * 16 + b_row) * SROW + ko + b_col) * 2;
                ldsm_x4(b[2 * jj][0], b[2 * jj][1],
                        b[2 * jj + 1][0], b[2 * jj + 1][1], addr);
            }
#pragma unroll
            for (int i = 0; i < 4; i++)
#pragma unroll
                for (int j = 0; j < 8; j++)
                    mma16816(d[i][j], a[i], b[j]);
        }

        // load ks3 frags of stage kt; MMA happens inside next barrier window
        {
            const int ko = 48;
#pragma unroll
            for (int i = 0; i < 4; i++) {
                uint32_t addr = sA_u +
                    (uint32_t)((wm + i * 16 + a_row) * SROW + ko + a_col) * 2;
                ldsm_x4(ah[i][0], ah[i][1], ah[i][2], ah[i][3], addr);
            }
#pragma unroll
            for (int jj = 0; jj < 4; jj++) {
                uint32_t addr = sB_u +
                    (uint32_t)((wn + jj * 16 + b_row) * SROW + ko + b_col) * 2;
                ldsm_x4(bh[2 * jj][0], bh[2 * jj][1],
                        bh[2 * jj + 1][0], bh[2 * jj + 1][1], addr);
            }
        }
    }

    // final held ks3 MMAs
#pragma unroll
    for (int i = 0; i < 4; i++)
#pragma unroll
        for (int j = 0; j < 8; j++)
            mma16816(d[i][j], ah[i], bh[j]);

    if (MODE == 0) {
        __half* C = (__half*)Cv;
#pragma unroll
        for (int i = 0; i < 4; i++) {
#pragma unroll
            for (int j = 0; j < 8; j++) {
                int col = n0 + wn + j * 8 + tg * 2;
                float s0 = vec[col], s1 = vec[col + 1];
                int r0 = m0 + wm + i * 16 + g;
                *(__half2*)(C + (size_t)r0 * N + col) =
                    __floats2half2_rn(d[i][j][0] * s0, d[i][j][1] * s1);
                *(__half2*)(C + (size_t)(r0 + 8) * N + col) =
                    __floats2half2_rn(d[i][j][2] * s0, d[i][j][3] * s1);
            }
        }
    } else {
        float* C = (float*)Cv;
#pragma unroll
        for (int i = 0; i < 4; i++) {
#pragma unroll
            for (int j = 0; j < 8; j++) {
                int col = n0 + wn + j * 8 + tg * 2;
                float b0 = vec[col], b1 = vec[col + 1];
                int r0 = m0 + wm + i * 16 + g;
                *(float2*)(C + (size_t)r0 * N + col) =
                    make_float2(d[i][j][0] * us + b0, d[i][j][1] * us + b1);
                *(float2*)(C + (size_t)(r0 + 8) * N + col) =
                    make_float2(d[i][j][2] * us + b0, d[i][j][3] * us + b1);
            }
        }
    }
}

// --------------------------- fused GEMM kernel ------------------------------
// bids [0, 512): GEMM1 tiles (m-major). bids [512, 2560): GEMM2 tiles (m-major).
__global__ void __launch_bounds__(128, 2)
fused_gemm(float* __restrict__ out,
           const float* __restrict__ uscale, const float* __restrict__ bias) {
    extern __shared__ char smc[];
    const int bid = blockIdx.x;

    if (bid < G1_TILES) {
        const int mb = bid >> 3;             // 8 n-tiles per m-block
        const int n0 = (bid & 7) * TN;
        gemm_body<0>(g_x16, g_W1, g_H, RANK, IN_F, g_hscale, 0.f,
                     mb * TM, n0, smc);
        __threadfence();
        __syncthreads();
        if (threadIdx.x == 0) atomicAdd(&g_flags[mb], 1);
    } else {
        const int b2 = bid - G1_TILES;
        const int mb = b2 >> 5;              // 32 n-tiles per m-block
        const int n0 = (b2 & 31) * TN;
        if (threadIdx.x == 0) {
            while (ld_acquire_gpu(&g_flags[mb]) < G1_TN_TILES) { }
        }
        __syncthreads();
        const float us = __ldg(uscale);
        gemm_body<1>(g_H, g_W2, out, OUT_F, RANK, bias, us,
                     mb * TM, n0, smc);
    }
}

// ------------------------------ launch -------------------------------------
extern "C" void kernel_launch(void* const* d_in, const int* in_sizes, int n_in,
                              void* d_out, int out_size) {
    const float* x        = (const float*)d_in[0];
    const int*   U_data   = (const int*)  d_in[1];
    const float* U_scale  = (const float*)d_in[2];
    const float* U_zp     = (const float*)d_in[3];
    const int*   S_data   = (const int*)  d_in[4];
    const float* S_scale  = (const float*)d_in[5];
    const float* S_zp     = (const float*)d_in[6];
    const int*   Vh_data  = (const int*)  d_in[7];
    const float* Vh_scale = (const float*)d_in[8];
    const float* Vh_zp    = (const float*)d_in[9];
    const float* bias     = (const float*)d_in[10];
    float* out = (float*)d_out;
    (void)in_sizes; (void)n_in; (void)out_size;

    cudaFuncSetAttribute(fused_gemm, cudaFuncAttributeMaxDynamicSharedMemorySize,
                         SMEM_USE);

    // prep: x->fp16, W1, W2, hscale, flag reset (one launch, high occupancy)
    {
        size_t total = NX_CH + NW1_CH + NW2_CH + RANK + MBLKS;
        prep_all<<<(unsigned)((total + 255) / 256), 256>>>(
            x, Vh_data, Vh_zp, U_data, U_zp, S_data, S_scale, S_zp, Vh_scale);
    }
    // fused GEMM1 + GEMM2 (flag-based cross-tile dependency)
    fused_gemm<<<G1_TILES + G2_TILES, 128, SMEM_USE>>>(out, U_scale, bias);
}